// round 1
// baseline (speedup 1.0000x reference)
#include <cuda_runtime.h>
#include <math.h>

#define BN 16384
#define NCS 64
#define NFS 128
#define NTOT 192
#define H 64

// ---------------- scratch (static device allocations) ----------------
__device__ float4 g_rgbd_c[BN * NCS];    // coarse MLP out: (rgb, density), index j*BN+b
__device__ float4 g_rgbd_f[BN * NTOT];   // fine MLP out
__device__ float  g_zt[NTOT * BN];       // fine z_vals, transposed: z[j*BN + b]

__device__ __forceinline__ float tval_of(float nb, float fb, int i) {
    float tt = (float)i * (1.0f / 63.0f);
    return nb * (1.0f - tt) + fb * tt;
}

// ---------------- MLP kernel: one thread per sample point ----------------
__global__ __launch_bounds__(128) void mlp_kernel(
    const float* __restrict__ origins, const float* __restrict__ dirs,
    const float* __restrict__ nearp,   const float* __restrict__ farp,
    const float* __restrict__ w1, const float* __restrict__ b1,
    const float* __restrict__ w2, const float* __restrict__ b2,
    const float* __restrict__ wr, const float* __restrict__ br,
    const float* __restrict__ wd, const float* __restrict__ bd,
    int use_z, float4* __restrict__ out_rgbd, int ns)
{
    __shared__ float  s_w1[3 * H];
    __shared__ float  s_b1[H];
    __shared__ float  s_w2t[H * H];   // s_w2t[j*H+k] = w2[k*H+j]
    __shared__ float  s_b2[H];
    __shared__ float4 s_head[H];      // (wr0, wr1, wr2, wd) per hidden unit
    __shared__ float  s_hb[4];        // br0, br1, br2, bd

    int tid = threadIdx.x;
    for (int i = tid; i < H * H; i += blockDim.x) {
        int j = i >> 6, k = i & 63;
        s_w2t[j * H + k] = w2[k * H + j];
    }
    for (int i = tid; i < H; i += blockDim.x) {
        s_b1[i] = b1[i];
        s_b2[i] = b2[i];
        s_w1[i]         = w1[i];
        s_w1[H + i]     = w1[H + i];
        s_w1[2 * H + i] = w1[2 * H + i];
        s_head[i] = make_float4(wr[i * 3 + 0], wr[i * 3 + 1], wr[i * 3 + 2], wd[i]);
    }
    if (tid < 3) s_hb[tid] = br[tid];
    if (tid == 3) s_hb[3] = bd[0];
    __syncthreads();

    unsigned int p = blockIdx.x * blockDim.x + tid;
    if (p >= (unsigned int)(ns * BN)) return;
    int b = (int)(p & (BN - 1));
    int j = (int)(p >> 14);

    float t;
    if (use_z) {
        t = g_zt[p];
    } else {
        t = tval_of(nearp[b], farp[b], j);
    }
    float ox = origins[3 * b], oy = origins[3 * b + 1], oz = origins[3 * b + 2];
    float dx = dirs[3 * b],    dy = dirs[3 * b + 1],    dz = dirs[3 * b + 2];
    float x = ox + t * dx, y = oy + t * dy, z = oz + t * dz;

    float h1[H];
    #pragma unroll
    for (int k = 0; k < H; k++) {
        float v = s_b1[k] + x * s_w1[k] + y * s_w1[H + k] + z * s_w1[2 * H + k];
        h1[k] = fmaxf(v, 0.0f);
    }

    float r0 = s_hb[0], r1 = s_hb[1], r2 = s_hb[2], dacc = s_hb[3];
    #pragma unroll 2
    for (int jj = 0; jj < H; jj++) {
        float a = s_b2[jj];
        const float4* wrow = reinterpret_cast<const float4*>(&s_w2t[jj * H]);
        #pragma unroll
        for (int k4 = 0; k4 < H / 4; k4++) {
            float4 wv = wrow[k4];
            int k = k4 * 4;
            a += h1[k] * wv.x + h1[k + 1] * wv.y + h1[k + 2] * wv.z + h1[k + 3] * wv.w;
        }
        a = fmaxf(a, 0.0f);
        float4 hw = s_head[jj];
        r0 += a * hw.x; r1 += a * hw.y; r2 += a * hw.z; dacc += a * hw.w;
    }

    float4 o;
    o.x = 1.0f / (1.0f + expf(-r0));
    o.y = 1.0f / (1.0f + expf(-r1));
    o.z = 1.0f / (1.0f + expf(-r2));
    o.w = fmaxf(dacc, 0.0f);
    out_rgbd[p] = o;
}

// ---------------- coarse render + inverse-CDF + merge : one thread per ray ----------------
__global__ __launch_bounds__(256) void render_coarse_kernel(
    const float* __restrict__ origins, const float* __restrict__ dirs,
    const float* __restrict__ nearp,   const float* __restrict__ farp,
    const float* __restrict__ bkgd,
    float* __restrict__ out)
{
    int b = blockIdx.x * blockDim.x + threadIdx.x;
    if (b >= BN) return;

    float nb = nearp[b], fb = farp[b];
    float n0 = nearp[0], f0 = farp[0];
    float dx = dirs[3 * b], dy = dirs[3 * b + 1], dz = dirs[3 * b + 2];
    float dn = sqrtf(dx * dx + dy * dy + dz * dz);

    float w[NCS];
    float T = 0.f, c0 = 0.f, c1 = 0.f, c2 = 0.f, acc = 0.f, depth = 0.f, s0 = 0.f;
    for (int j = 0; j < NCS; j++) {
        float tj  = tval_of(nb, fb, j);
        float tdist = (j < NCS - 1) ? (tval_of(nb, fb, j + 1) - tj) : 1e10f;
        float4 rd = g_rgbd_c[j * BN + b];
        float dd = rd.w * tdist * dn;
        float alpha = 1.0f - expf(-dd);
        float trans = expf(-T);
        float wj = alpha * trans;
        T += dd;
        w[j] = wj;
        c0 += wj * rd.x; c1 += wj * rd.y; c2 += wj * rd.z;
        acc += wj;
        depth += wj * tj;
        s0 += wj * tval_of(n0, f0, j);
    }
    c0 += bkgd[0] * (1.0f - acc);
    c1 += bkgd[1] * (1.0f - acc);
    c2 += bkgd[2] * (1.0f - acc);

    float o0x = origins[0], o0y = origins[1], o0z = origins[2];
    float d0x = dirs[0],    d0y = dirs[1],    d0z = dirs[2];
    float* po = out + (size_t)b * 16;
    po[0] = c0; po[1] = c1; po[2] = c2;
    po[3] = depth; po[4] = acc;
    po[5] = acc * o0x + s0 * d0x;
    po[6] = acc * o0y + s0 * d0y;
    po[7] = acc * o0z + s0 * d0z;

    // ---- piecewise-constant PDF inverse-CDF sampling ----
    float ws = 0.f;
    for (int i = 0; i < 62; i++) ws += w[i + 1];
    float pad  = fmaxf(1e-5f - ws, 0.f);
    float padd = pad * (1.0f / 62.0f);
    ws += pad;
    float inv_ws = 1.0f / ws;

    float cdf[63];
    cdf[0] = 0.f;
    float run = 0.f;
    for (int i = 1; i <= 61; i++) {
        run += (w[i] + padd) * inv_ws;   // pdf[i-1]
        cdf[i] = fminf(run, 1.f);
    }
    cdf[62] = 1.f;

    const float F32EPS = 1.1920928955078125e-7f;
    const float ustep = (1.0f - F32EPS) * (1.0f / 127.0f);
    int i0 = 0;
    int ti = 0;     // merge pointer into t_vals
    int outn = 0;   // merged output count
    for (int s = 0; s < NFS; s++) {
        float u = (float)s * ustep;
        while (i0 + 1 < 62 + 1 && cdf[i0 + 1] <= u) i0++;   // largest i with cdf[i] <= u
        float cg0 = cdf[i0], cg1 = cdf[i0 + 1];
        float bg0 = 0.5f * (tval_of(nb, fb, i0)     + tval_of(nb, fb, i0 + 1));
        float bg1 = 0.5f * (tval_of(nb, fb, i0 + 1) + tval_of(nb, fb, i0 + 2));
        float denom = cg1 - cg0;
        float tf = (denom > 0.f) ? (u - cg0) / denom : 0.f;
        tf = fminf(fmaxf(tf, 0.f), 1.f);
        float zs = bg0 + tf * (bg1 - bg0);
        // stream-merge with the (sorted) coarse t_vals
        while (ti < NCS && tval_of(nb, fb, ti) <= zs) {
            g_zt[outn * BN + b] = tval_of(nb, fb, ti);
            outn++; ti++;
        }
        g_zt[outn * BN + b] = zs;
        outn++;
    }
    while (ti < NCS) {
        g_zt[outn * BN + b] = tval_of(nb, fb, ti);
        outn++; ti++;
    }
}

// ---------------- fine render : one thread per ray ----------------
__global__ __launch_bounds__(256) void render_fine_kernel(
    const float* __restrict__ origins, const float* __restrict__ dirs,
    const float* __restrict__ bkgd,
    float* __restrict__ out)
{
    int b = blockIdx.x * blockDim.x + threadIdx.x;
    if (b >= BN) return;

    float dx = dirs[3 * b], dy = dirs[3 * b + 1], dz = dirs[3 * b + 2];
    float dn = sqrtf(dx * dx + dy * dy + dz * dz);

    float T = 0.f, c0 = 0.f, c1 = 0.f, c2 = 0.f, acc = 0.f, depth = 0.f, s1 = 0.f;
    float zj = g_zt[b];  // j = 0
    for (int j = 0; j < NTOT; j++) {
        float zj1 = (j < NTOT - 1) ? g_zt[(j + 1) * BN + b] : 0.f;
        float tdist = (j < NTOT - 1) ? (zj1 - zj) : 1e10f;
        float4 rd = g_rgbd_f[j * BN + b];
        float dd = rd.w * tdist * dn;
        float alpha = 1.0f - expf(-dd);
        float wj = alpha * expf(-T);
        T += dd;
        c0 += wj * rd.x; c1 += wj * rd.y; c2 += wj * rd.z;
        acc += wj;
        depth += wj * zj;
        s1 += wj * g_zt[j * BN];   // ray 0's z (the samples_f[0] quirk)
        zj = zj1;
    }
    c0 += bkgd[0] * (1.0f - acc);
    c1 += bkgd[1] * (1.0f - acc);
    c2 += bkgd[2] * (1.0f - acc);

    float o0x = origins[0], o0y = origins[1], o0z = origins[2];
    float d0x = dirs[0],    d0y = dirs[1],    d0z = dirs[2];
    float* po = out + (size_t)b * 16;
    po[8]  = c0; po[9] = c1; po[10] = c2;
    po[11] = depth; po[12] = acc;
    po[13] = acc * o0x + s1 * d0x;
    po[14] = acc * o0y + s1 * d0y;
    po[15] = acc * o0z + s1 * d0z;
}

// ---------------- launch ----------------
extern "C" void kernel_launch(void* const* d_in, const int* in_sizes, int n_in,
                              void* d_out, int out_size)
{
    const float* origins = (const float*)d_in[0];
    const float* dirs    = (const float*)d_in[1];
    const float* nearp   = (const float*)d_in[2];
    const float* farp    = (const float*)d_in[3];
    const float* bkgd    = (const float*)d_in[4];
    const float* w1_c = (const float*)d_in[5];
    const float* b1_c = (const float*)d_in[6];
    const float* w2_c = (const float*)d_in[7];
    const float* b2_c = (const float*)d_in[8];
    const float* wr_c = (const float*)d_in[9];
    const float* br_c = (const float*)d_in[10];
    const float* wd_c = (const float*)d_in[11];
    const float* bd_c = (const float*)d_in[12];
    const float* w1_f = (const float*)d_in[13];
    const float* b1_f = (const float*)d_in[14];
    const float* w2_f = (const float*)d_in[15];
    const float* b2_f = (const float*)d_in[16];
    const float* wr_f = (const float*)d_in[17];
    const float* br_f = (const float*)d_in[18];
    const float* wd_f = (const float*)d_in[19];
    const float* bd_f = (const float*)d_in[20];
    float* out = (float*)d_out;

    float4* rgbd_c;
    float4* rgbd_f;
    cudaGetSymbolAddress((void**)&rgbd_c, g_rgbd_c);
    cudaGetSymbolAddress((void**)&rgbd_f, g_rgbd_f);

    // 1) coarse MLP over 64*B points
    {
        int total = NCS * BN;
        mlp_kernel<<<total / 128, 128>>>(origins, dirs, nearp, farp,
                                         w1_c, b1_c, w2_c, b2_c, wr_c, br_c, wd_c, bd_c,
                                         0, rgbd_c, NCS);
    }
    // 2) coarse render + PDF sample + merge
    render_coarse_kernel<<<BN / 256, 256>>>(origins, dirs, nearp, farp, bkgd, out);
    // 3) fine MLP over 192*B points
    {
        int total = NTOT * BN;
        mlp_kernel<<<total / 128, 128>>>(origins, dirs, nearp, farp,
                                         w1_f, b1_f, w2_f, b2_f, wr_f, br_f, wd_f, bd_f,
                                         1, rgbd_f, NTOT);
    }
    // 4) fine render
    render_fine_kernel<<<BN / 256, 256>>>(origins, dirs, bkgd, out);
}

// round 5
// speedup vs baseline: 1.2267x; 1.2267x over previous
#include <cuda_runtime.h>
#include <math.h>

#define BN 16384
#define NCS 64
#define NFS 128
#define NTOT 192
#define H 64

typedef unsigned long long u64;

// ---------------- scratch ----------------
__device__ float4 g_rgbd_c[BN * NCS];
__device__ float4 g_rgbd_f[BN * NTOT];
__device__ float  g_zt[NTOT * BN];       // fine z_vals transposed: z[j*BN + b]

__device__ __forceinline__ float tval_of(float nb, float fb, int i) {
    float tt = (float)i * (1.0f / 63.0f);
    return nb * (1.0f - tt) + fb * tt;
}

// ---- f32x2 packed helpers ----
__device__ __forceinline__ u64 pk2(float lo, float hi) {
    u64 r; asm("mov.b64 %0, {%1, %2};" : "=l"(r) : "f"(lo), "f"(hi)); return r;
}
__device__ __forceinline__ void upk2(u64 v, float& lo, float& hi) {
    asm("mov.b64 {%0, %1}, %2;" : "=f"(lo), "=f"(hi) : "l"(v));
}
__device__ __forceinline__ u64 ffma2(u64 a, u64 b, u64 c) {
    u64 d; asm("fma.rn.f32x2 %0, %1, %2, %3;" : "=l"(d) : "l"(a), "l"(b), "l"(c)); return d;
}
__device__ __forceinline__ u64 add2(u64 a, u64 b) {
    u64 d; asm("add.rn.f32x2 %0, %1, %2;" : "=l"(d) : "l"(a), "l"(b)); return d;
}
__device__ __forceinline__ u64 relu2(u64 v) {
    float a, b; upk2(v, a, b);
    return pk2(fmaxf(a, 0.0f), fmaxf(b, 0.0f));
}

// ---------------- packed MLP: one thread = 2 points of one ray ----------------
__global__ __launch_bounds__(128) void mlp2_kernel(
    const float* __restrict__ origins, const float* __restrict__ dirs,
    const float* __restrict__ nearp,   const float* __restrict__ farp,
    const float* __restrict__ w1, const float* __restrict__ b1,
    const float* __restrict__ w2, const float* __restrict__ b2,
    const float* __restrict__ wr, const float* __restrict__ br,
    const float* __restrict__ wd, const float* __restrict__ bd,
    int use_z, float4* __restrict__ out_rgbd, int ns2)
{
    __shared__ u64 s_w1x[H], s_w1y[H], s_w1z[H], s_b1[H], s_b2[H];
    __shared__ ulonglong2 s_w2v[H * H / 2];   // [jj][k/2]: dup-packed transposed W2
    __shared__ ulonglong2 s_hv[H * 2];        // [jj]: {dup wr0, dup wr1},{dup wr2, dup wd}
    __shared__ float s_hb[4];

    int tid = threadIdx.x;
    for (int i = tid; i < H * H / 2; i += blockDim.x) {
        int jj = i >> 5, k2 = i & 31;
        float a = w2[(2 * k2) * H + jj];
        float c = w2[(2 * k2 + 1) * H + jj];
        s_w2v[jj * (H / 2) + k2] = make_ulonglong2(pk2(a, a), pk2(c, c));
    }
    for (int i = tid; i < H; i += blockDim.x) {
        s_w1x[i] = pk2(w1[i], w1[i]);
        s_w1y[i] = pk2(w1[H + i], w1[H + i]);
        s_w1z[i] = pk2(w1[2 * H + i], w1[2 * H + i]);
        s_b1[i]  = pk2(b1[i], b1[i]);
        s_b2[i]  = pk2(b2[i], b2[i]);
        s_hv[2 * i]     = make_ulonglong2(pk2(wr[3 * i], wr[3 * i]), pk2(wr[3 * i + 1], wr[3 * i + 1]));
        s_hv[2 * i + 1] = make_ulonglong2(pk2(wr[3 * i + 2], wr[3 * i + 2]), pk2(wd[i], wd[i]));
    }
    if (tid < 3) s_hb[tid] = br[tid];
    if (tid == 3) s_hb[3] = bd[0];
    __syncthreads();

    unsigned p = blockIdx.x * blockDim.x + tid;   // grid sized exactly ns2*BN/128
    int b = (int)(p & (BN - 1));
    int j = (int)(p >> 14);

    float t0, t1;
    if (use_z) {
        t0 = g_zt[j * BN + b];
        t1 = g_zt[(j + ns2) * BN + b];
    } else {
        float nb = nearp[b], fb = farp[b];
        t0 = tval_of(nb, fb, j);
        t1 = tval_of(nb, fb, j + ns2);
    }
    float ox = origins[3 * b], oy = origins[3 * b + 1], oz = origins[3 * b + 2];
    float dx = dirs[3 * b],    dy = dirs[3 * b + 1],    dz = dirs[3 * b + 2];
    u64 xp = pk2(ox + t0 * dx, ox + t1 * dx);
    u64 yp = pk2(oy + t0 * dy, oy + t1 * dy);
    u64 zp = pk2(oz + t0 * dz, oz + t1 * dz);

    u64 h1[H];
    #pragma unroll
    for (int k = 0; k < H; k++) {
        u64 v = ffma2(xp, s_w1x[k], s_b1[k]);
        v = ffma2(yp, s_w1y[k], v);
        v = ffma2(zp, s_w1z[k], v);
        h1[k] = relu2(v);
    }

    u64 r0 = pk2(s_hb[0], s_hb[0]);
    u64 r1 = pk2(s_hb[1], s_hb[1]);
    u64 r2 = pk2(s_hb[2], s_hb[2]);
    u64 rd_ = pk2(s_hb[3], s_hb[3]);
    u64 zero = pk2(0.f, 0.f);

    for (int jj = 0; jj < H; jj++) {
        const ulonglong2* wrow = &s_w2v[jj * (H / 2)];
        u64 a0 = s_b2[jj], a1 = zero, a2 = zero, a3 = zero;
        #pragma unroll
        for (int k2 = 0; k2 < H / 2; k2 += 4) {
            ulonglong2 wv0 = wrow[k2];
            ulonglong2 wv1 = wrow[k2 + 1];
            ulonglong2 wv2 = wrow[k2 + 2];
            ulonglong2 wv3 = wrow[k2 + 3];
            a0 = ffma2(h1[2 * k2 + 0], wv0.x, a0);
            a1 = ffma2(h1[2 * k2 + 1], wv0.y, a1);
            a2 = ffma2(h1[2 * k2 + 2], wv1.x, a2);
            a3 = ffma2(h1[2 * k2 + 3], wv1.y, a3);
            a0 = ffma2(h1[2 * k2 + 4], wv2.x, a0);
            a1 = ffma2(h1[2 * k2 + 5], wv2.y, a1);
            a2 = ffma2(h1[2 * k2 + 6], wv3.x, a2);
            a3 = ffma2(h1[2 * k2 + 7], wv3.y, a3);
        }
        u64 a = relu2(add2(add2(a0, a1), add2(a2, a3)));
        ulonglong2 hv0 = s_hv[2 * jj], hv1 = s_hv[2 * jj + 1];
        r0 = ffma2(a, hv0.x, r0);
        r1 = ffma2(a, hv0.y, r1);
        r2 = ffma2(a, hv1.x, r2);
        rd_ = ffma2(a, hv1.y, rd_);
    }

    float lo, hi;
    float4 o0, o1;
    upk2(r0, lo, hi); o0.x = 1.f / (1.f + expf(-lo)); o1.x = 1.f / (1.f + expf(-hi));
    upk2(r1, lo, hi); o0.y = 1.f / (1.f + expf(-lo)); o1.y = 1.f / (1.f + expf(-hi));
    upk2(r2, lo, hi); o0.z = 1.f / (1.f + expf(-lo)); o1.z = 1.f / (1.f + expf(-hi));
    upk2(rd_, lo, hi); o0.w = fmaxf(lo, 0.f); o1.w = fmaxf(hi, 0.f);
    out_rgbd[j * BN + b] = o0;
    out_rgbd[(j + ns2) * BN + b] = o1;
}

// ---------------- coarse render + inverse-CDF + merge : one thread per ray (R1, verified) ----------------
__global__ __launch_bounds__(128) void render_coarse_kernel(
    const float* __restrict__ origins, const float* __restrict__ dirs,
    const float* __restrict__ nearp,   const float* __restrict__ farp,
    const float* __restrict__ bkgd,
    float* __restrict__ out)
{
    int b = blockIdx.x * blockDim.x + threadIdx.x;
    if (b >= BN) return;

    float nb = nearp[b], fb = farp[b];
    float n0 = nearp[0], f0 = farp[0];
    float dx = dirs[3 * b], dy = dirs[3 * b + 1], dz = dirs[3 * b + 2];
    float dn = sqrtf(dx * dx + dy * dy + dz * dz);

    float w[NCS];
    float T = 0.f, c0 = 0.f, c1 = 0.f, c2 = 0.f, acc = 0.f, depth = 0.f, s0 = 0.f;
    for (int j = 0; j < NCS; j++) {
        float tj  = tval_of(nb, fb, j);
        float tdist = (j < NCS - 1) ? (tval_of(nb, fb, j + 1) - tj) : 1e10f;
        float4 rd = g_rgbd_c[j * BN + b];
        float dd = rd.w * tdist * dn;
        float alpha = 1.0f - expf(-dd);
        float trans = expf(-T);
        float wj = alpha * trans;
        T += dd;
        w[j] = wj;
        c0 += wj * rd.x; c1 += wj * rd.y; c2 += wj * rd.z;
        acc += wj;
        depth += wj * tj;
        s0 += wj * tval_of(n0, f0, j);
    }
    c0 += bkgd[0] * (1.0f - acc);
    c1 += bkgd[1] * (1.0f - acc);
    c2 += bkgd[2] * (1.0f - acc);

    float o0x = origins[0], o0y = origins[1], o0z = origins[2];
    float d0x = dirs[0],    d0y = dirs[1],    d0z = dirs[2];
    float* po = out + (size_t)b * 16;
    po[0] = c0; po[1] = c1; po[2] = c2;
    po[3] = depth; po[4] = acc;
    po[5] = acc * o0x + s0 * d0x;
    po[6] = acc * o0y + s0 * d0y;
    po[7] = acc * o0z + s0 * d0z;

    // ---- piecewise-constant PDF inverse-CDF sampling ----
    float ws = 0.f;
    for (int i = 0; i < 62; i++) ws += w[i + 1];
    float pad  = fmaxf(1e-5f - ws, 0.f);
    float padd = pad * (1.0f / 62.0f);
    ws += pad;
    float inv_ws = 1.0f / ws;

    float cdf[63];
    cdf[0] = 0.f;
    float run = 0.f;
    for (int i = 1; i <= 61; i++) {
        run += (w[i] + padd) * inv_ws;   // pdf[i-1]
        cdf[i] = fminf(run, 1.f);
    }
    cdf[62] = 1.f;

    const float F32EPS = 1.1920928955078125e-7f;
    const float ustep = (1.0f - F32EPS) * (1.0f / 127.0f);
    int i0 = 0;
    int ti = 0;     // merge pointer into t_vals
    int outn = 0;   // merged output count
    for (int s = 0; s < NFS; s++) {
        float u = (float)s * ustep;
        while (i0 + 1 < 62 + 1 && cdf[i0 + 1] <= u) i0++;   // largest i with cdf[i] <= u
        float cg0 = cdf[i0], cg1 = cdf[i0 + 1];
        float bg0 = 0.5f * (tval_of(nb, fb, i0)     + tval_of(nb, fb, i0 + 1));
        float bg1 = 0.5f * (tval_of(nb, fb, i0 + 1) + tval_of(nb, fb, i0 + 2));
        float denom = cg1 - cg0;
        float tf = (denom > 0.f) ? (u - cg0) / denom : 0.f;
        tf = fminf(fmaxf(tf, 0.f), 1.f);
        float zs = bg0 + tf * (bg1 - bg0);
        // stream-merge with the (sorted) coarse t_vals
        while (ti < NCS && tval_of(nb, fb, ti) <= zs) {
            g_zt[outn * BN + b] = tval_of(nb, fb, ti);
            outn++; ti++;
        }
        g_zt[outn * BN + b] = zs;
        outn++;
    }
    while (ti < NCS) {
        g_zt[outn * BN + b] = tval_of(nb, fb, ti);
        outn++; ti++;
    }
}

// ---------------- fine render : one thread per ray (R1, verified) ----------------
__global__ __launch_bounds__(128) void render_fine_kernel(
    const float* __restrict__ origins, const float* __restrict__ dirs,
    const float* __restrict__ bkgd,
    float* __restrict__ out)
{
    int b = blockIdx.x * blockDim.x + threadIdx.x;
    if (b >= BN) return;

    float dx = dirs[3 * b], dy = dirs[3 * b + 1], dz = dirs[3 * b + 2];
    float dn = sqrtf(dx * dx + dy * dy + dz * dz);

    float T = 0.f, c0 = 0.f, c1 = 0.f, c2 = 0.f, acc = 0.f, depth = 0.f, s1 = 0.f;
    float zj = g_zt[b];  // j = 0
    for (int j = 0; j < NTOT; j++) {
        float zj1 = (j < NTOT - 1) ? g_zt[(j + 1) * BN + b] : 0.f;
        float tdist = (j < NTOT - 1) ? (zj1 - zj) : 1e10f;
        float4 rd = g_rgbd_f[j * BN + b];
        float dd = rd.w * tdist * dn;
        float alpha = 1.0f - expf(-dd);
        float wj = alpha * expf(-T);
        T += dd;
        c0 += wj * rd.x; c1 += wj * rd.y; c2 += wj * rd.z;
        acc += wj;
        depth += wj * zj;
        s1 += wj * g_zt[j * BN];   // ray 0's z (the samples_f[0] quirk)
        zj = zj1;
    }
    c0 += bkgd[0] * (1.0f - acc);
    c1 += bkgd[1] * (1.0f - acc);
    c2 += bkgd[2] * (1.0f - acc);

    float o0x = origins[0], o0y = origins[1], o0z = origins[2];
    float d0x = dirs[0],    d0y = dirs[1],    d0z = dirs[2];
    float* po = out + (size_t)b * 16;
    po[8]  = c0; po[9] = c1; po[10] = c2;
    po[11] = depth; po[12] = acc;
    po[13] = acc * o0x + s1 * d0x;
    po[14] = acc * o0y + s1 * d0y;
    po[15] = acc * o0z + s1 * d0z;
}

// ---------------- launch ----------------
extern "C" void kernel_launch(void* const* d_in, const int* in_sizes, int n_in,
                              void* d_out, int out_size)
{
    const float* origins = (const float*)d_in[0];
    const float* dirs    = (const float*)d_in[1];
    const float* nearp   = (const float*)d_in[2];
    const float* farp    = (const float*)d_in[3];
    const float* bkgd    = (const float*)d_in[4];
    const float* w1_c = (const float*)d_in[5];
    const float* b1_c = (const float*)d_in[6];
    const float* w2_c = (const float*)d_in[7];
    const float* b2_c = (const float*)d_in[8];
    const float* wr_c = (const float*)d_in[9];
    const float* br_c = (const float*)d_in[10];
    const float* wd_c = (const float*)d_in[11];
    const float* bd_c = (const float*)d_in[12];
    const float* w1_f = (const float*)d_in[13];
    const float* b1_f = (const float*)d_in[14];
    const float* w2_f = (const float*)d_in[15];
    const float* b2_f = (const float*)d_in[16];
    const float* wr_f = (const float*)d_in[17];
    const float* br_f = (const float*)d_in[18];
    const float* wd_f = (const float*)d_in[19];
    const float* bd_f = (const float*)d_in[20];
    float* out = (float*)d_out;

    float4* rgbd_c;
    float4* rgbd_f;
    cudaGetSymbolAddress((void**)&rgbd_c, g_rgbd_c);
    cudaGetSymbolAddress((void**)&rgbd_f, g_rgbd_f);

    // 1) coarse MLP: 32 pairs * BN rays
    mlp2_kernel<<<(NCS / 2) * BN / 128, 128>>>(origins, dirs, nearp, farp,
                                               w1_c, b1_c, w2_c, b2_c, wr_c, br_c, wd_c, bd_c,
                                               0, rgbd_c, NCS / 2);
    // 2) coarse render + PDF sample + stream merge (serial, verified)
    render_coarse_kernel<<<BN / 128, 128>>>(origins, dirs, nearp, farp, bkgd, out);
    // 3) fine MLP: 96 pairs * BN rays
    mlp2_kernel<<<(NTOT / 2) * BN / 128, 128>>>(origins, dirs, nearp, farp,
                                                w1_f, b1_f, w2_f, b2_f, wr_f, br_f, wd_f, bd_f,
                                                1, rgbd_f, NTOT / 2);
    // 4) fine render (serial, verified)
    render_fine_kernel<<<BN / 128, 128>>>(origins, dirs, bkgd, out);
}